// round 16
// baseline (speedup 1.0000x reference)
#include <cuda_runtime.h>
#include <cuda_bf16.h>

// Problem constants
#define NB 128          // graphs
#define NN 512          // nodes per graph
#define NNODES (NB*NN)  // 65536
#define NE 524288       // edges
#define EPG 4096        // edges per graph
#define EPT 8           // edges per thread in build (4096/512)
#define F_IN 128
#define H1 64
#define H2 128
#define NC 10
#define KSEL 410        // ceil(0.8*512)
#define FQ 16           // features per gather block (quarter of H1)

// ---------------- scratch (static device globals; no allocation) ----------------
__device__ __align__(16) int            g_rowstart[NNODES];  // per-node excl. offset within graph
__device__ __align__(16) unsigned short g_col16[NE];         // local src ids, CSR order per graph
__device__ __align__(16) float          g_dis[NNODES];
__device__ __align__(16) float          g_h1[NNODES * H1];
__device__ __align__(16) float          g_a2[NNODES * H1];
__device__ __align__(16) float          g_out2[NNODES * H2];
__device__ __align__(16) float          g_score[NNODES];

// ---------------- fused per-graph CSR build ----------------
__global__ void k_build(const int* __restrict__ ei) {
    __shared__ int cnt[NN];
    __shared__ int scn[NN];
    __shared__ int fill[NN];
    int b = blockIdx.x, t = threadIdx.x;
    cnt[t] = 0;
    __syncthreads();

    int ebase = b * EPG;
    int sl[EPT], dl[EPT];
    #pragma unroll
    for (int j = 0; j < EPT; j++) {
        int e = ebase + j * NN + t;           // coalesced
        sl[j] = ei[e] & (NN - 1);             // local ids (graph offset removed by mask)
        dl[j] = ei[NE + e] & (NN - 1);
        atomicAdd(&cnt[dl[j]], 1);
    }
    __syncthreads();

    int c = cnt[t];
    scn[t] = c;
    __syncthreads();
    #pragma unroll
    for (int off = 1; off < NN; off <<= 1) {
        int v = (t >= off) ? scn[t - off] : 0;
        __syncthreads();
        scn[t] += v;
        __syncthreads();
    }
    int excl = scn[t] - c;
    int gv = b * NN + t;
    g_rowstart[gv] = excl;
    g_dis[gv] = rsqrtf((float)(c + 1));       // +1 self loop
    fill[t] = excl;
    __syncthreads();

    #pragma unroll
    for (int j = 0; j < EPT; j++) {
        int pos = atomicAdd(&fill[dl[j]], 1);
        g_col16[ebase + pos] = (unsigned short)sl[j];
    }
}

// ---------------- GEMM1: g_h1[65536,64] = X[65536,128] @ W1[128,64] ----------------
__global__ void k_gemm1(const float* __restrict__ X, const float* __restrict__ W) {
    __shared__ float Ws[F_IN * H1];    // 32 KB
    __shared__ float Xs[32 * F_IN];    // 16 KB
    int tx = threadIdx.x, ty = threadIdx.y;
    int t = ty * 16 + tx;
    int row0 = blockIdx.x * 32;

    float4* Ws4 = (float4*)Ws;
    const float4* Wg = (const float4*)W;
    #pragma unroll
    for (int l = t; l < (F_IN * H1) / 4; l += 128) Ws4[l] = Wg[l];

    float4* Xs4 = (float4*)Xs;
    const float4* Xg = (const float4*)(X + (size_t)row0 * F_IN);
    #pragma unroll
    for (int l = t; l < (32 * F_IN) / 4; l += 128) Xs4[l] = Xg[l];
    __syncthreads();

    float acc[4][4];
    #pragma unroll
    for (int r = 0; r < 4; r++)
        #pragma unroll
        for (int c = 0; c < 4; c++) acc[r][c] = 0.f;

    #pragma unroll 4
    for (int k = 0; k < F_IN; k += 4) {
        float4 xq[4];
        #pragma unroll
        for (int r = 0; r < 4; r++) xq[r] = Xs4[(ty * 4 + r) * (F_IN / 4) + k / 4];
        #pragma unroll
        for (int kk = 0; kk < 4; kk++) {
            float4 w = Ws4[(k + kk) * (H1 / 4) + tx];
            #pragma unroll
            for (int r = 0; r < 4; r++) {
                float xv = (kk == 0) ? xq[r].x : (kk == 1) ? xq[r].y : (kk == 2) ? xq[r].z : xq[r].w;
                acc[r][0] += xv * w.x;
                acc[r][1] += xv * w.y;
                acc[r][2] += xv * w.z;
                acc[r][3] += xv * w.w;
            }
        }
    }
    #pragma unroll
    for (int r = 0; r < 4; r++) {
        float4 o = make_float4(acc[r][0], acc[r][1], acc[r][2], acc[r][3]);
        ((float4*)g_h1)[((size_t)(row0 + ty * 4 + r) * H1 + tx * 4) / 4] = o;
    }
}

// ---------------- fused double gather, one (graph, feature-quarter) per block ----------------
// pass0: o1 = relu( dis[v]*(hs'[v] + sum hs'[col]) + b1 )   (hs' = dis*h1)
// then hs <- dis*o1, pass1: a2 = dis[v]*(hs'[v] + sum hs'[col])
// smem: hs 512*16*4=32KB + rs 2052B + cols 8KB = 42 KB -> 4 blocks/SM (thread-limited), grid 512 = 1 wave
__global__ void k_gatherF(const float* __restrict__ bias) {
    extern __shared__ float smem[];
    float* hs = smem;                                      // NN*FQ floats
    int*   rs = (int*)(smem + NN * FQ);                    // NN+1 ints
    unsigned short* cols = (unsigned short*)(rs + NN + 1); // EPG u16

    int b = blockIdx.x, q = blockIdx.y, t = threadIdx.x;   // 512 threads
    int gbase = b * NN;
    int ebase = b * EPG;

    // stage cols (4096 u16 = 2048 u32)
    {
        const unsigned int* gc = (const unsigned int*)(g_col16 + ebase);
        unsigned int* sc = (unsigned int*)cols;
        #pragma unroll
        for (int j = 0; j < 4; j++) sc[j * NN + t] = gc[j * NN + t];
    }
    rs[t] = g_rowstart[gbase + t];
    if (t == 0) rs[NN] = EPG;

    // stage feature quarter pre-scaled by dis: hs[node][16]; 2048 float4 total
    {
        float4* hs4 = (float4*)hs;
        const float4* g4 = (const float4*)g_h1;
        #pragma unroll
        for (int j = 0; j < 4; j++) {
            int idx = j * NN + t;          // 0..2047
            int node = idx >> 2, qq = idx & 3;
            float dn = g_dis[gbase + node];
            float4 v = g4[(size_t)(gbase + node) * 16 + q * 4 + qq];
            v.x *= dn; v.y *= dn; v.z *= dn; v.w *= dn;
            hs4[idx] = v;
        }
    }
    __syncthreads();

    int warp = t >> 5, lane = t & 31;
    int fl = lane & 15, hi = lane >> 4;    // feature lane, edge-parity half
    int v0 = warp * 32;                    // 32 contiguous nodes per warp
    float dvreg = g_dis[gbase + v0 + lane];
    float bb = bias[q * FQ + fl];
    const float* hl = hs + fl;

    float o1[32];                          // pass-0 results (lanes<16 meaningful)

    // ---- pass 0 ----
    #pragma unroll
    for (int i = 0; i < 32; i++) {
        int v = v0 + i;
        int beg = rs[v], end = rs[v + 1];
        float a = (hi == 0) ? hl[v * FQ] : 0.f;    // self term once
        for (int e = beg + hi; e < end; e += 2) {
            int s = cols[e];
            a += hl[s * FQ];
        }
        a += __shfl_down_sync(0xffffffffu, a, 16);
        float dv = __shfl_sync(0xffffffffu, dvreg, i);
        o1[i] = fmaxf(fmaf(dv, a, bb), 0.f);
    }
    __syncthreads();
    // re-stage: hs <- dis * o1
    #pragma unroll
    for (int i = 0; i < 32; i++) {
        int v = v0 + i;
        float dv = __shfl_sync(0xffffffffu, dvreg, i);
        if (hi == 0) hs[v * FQ + fl] = dv * o1[i];
    }
    __syncthreads();

    // ---- pass 1 ----
    #pragma unroll
    for (int i = 0; i < 32; i++) {
        int v = v0 + i;
        int beg = rs[v], end = rs[v + 1];
        float a = (hi == 0) ? hl[v * FQ] : 0.f;
        for (int e = beg + hi; e < end; e += 2) {
            int s = cols[e];
            a += hl[s * FQ];
        }
        a += __shfl_down_sync(0xffffffffu, a, 16);
        float dv = __shfl_sync(0xffffffffu, dvreg, i);
        if (hi == 0) g_a2[(size_t)(gbase + v) * H1 + q * FQ + fl] = dv * a;
    }
}

// ---------------- GEMM2 + fused score: g_out2 = relu(g_a2 @ W2 + b2), g_score = out2.pw/||pw|| ----------------
__global__ void k_gemm2(const float* __restrict__ W, const float* __restrict__ bias,
                        const float* __restrict__ pw) {
    __shared__ float Ws[H1 * H2];   // 32 KB
    __shared__ float Xs[64 * H1];   // 16 KB
    int tx = threadIdx.x, ty = threadIdx.y;
    int t = ty * 32 + tx;
    int row0 = blockIdx.x * 64;

    float4* Ws4 = (float4*)Ws;
    const float4* Wg = (const float4*)W;
    #pragma unroll
    for (int l = t; l < (H1 * H2) / 4; l += 256) Ws4[l] = Wg[l];

    float4* Xs4 = (float4*)Xs;
    const float4* Ag = (const float4*)(g_a2 + (size_t)row0 * H1);
    #pragma unroll
    for (int l = t; l < (64 * H1) / 4; l += 256) Xs4[l] = Ag[l];
    __syncthreads();

    float acc[8][4];
    #pragma unroll
    for (int r = 0; r < 8; r++)
        #pragma unroll
        for (int c = 0; c < 4; c++) acc[r][c] = 0.f;

    #pragma unroll 2
    for (int k = 0; k < H1; k += 4) {
        float4 xq[8];
        #pragma unroll
        for (int r = 0; r < 8; r++) xq[r] = Xs4[(ty * 8 + r) * (H1 / 4) + k / 4];
        #pragma unroll
        for (int kk = 0; kk < 4; kk++) {
            float4 w = Ws4[(k + kk) * (H2 / 4) + tx];
            #pragma unroll
            for (int r = 0; r < 8; r++) {
                float xv = (kk == 0) ? xq[r].x : (kk == 1) ? xq[r].y : (kk == 2) ? xq[r].z : xq[r].w;
                acc[r][0] += xv * w.x;
                acc[r][1] += xv * w.y;
                acc[r][2] += xv * w.z;
                acc[r][3] += xv * w.w;
            }
        }
    }

    float4 bq = ((const float4*)bias)[tx];
    float4 p  = ((const float4*)pw)[tx];
    float nn = p.x * p.x + p.y * p.y + p.z * p.z + p.w * p.w;
    #pragma unroll
    for (int off = 16; off > 0; off >>= 1) nn += __shfl_xor_sync(0xffffffffu, nn, off);
    float rn = rsqrtf(nn);

    #pragma unroll
    for (int r = 0; r < 8; r++) {
        float4 o;
        o.x = fmaxf(acc[r][0] + bq.x, 0.f);
        o.y = fmaxf(acc[r][1] + bq.y, 0.f);
        o.z = fmaxf(acc[r][2] + bq.z, 0.f);
        o.w = fmaxf(acc[r][3] + bq.w, 0.f);
        int row = row0 + ty * 8 + r;
        ((float4*)g_out2)[((size_t)row * H2 + tx * 4) / 4] = o;
        float sp = o.x * p.x + o.y * p.y + o.z * p.z + o.w * p.w;
        #pragma unroll
        for (int off = 16; off > 0; off >>= 1) sp += __shfl_xor_sync(0xffffffffu, sp, off);
        if (tx == 0) g_score[row] = sp * rn;
    }
}

// ---------------- top-K + gated global max pool + FC + log_softmax, one block per graph ----------------
__global__ void k_pool(const float* __restrict__ fcW, const float* __restrict__ fcb,
                       float* __restrict__ out) {
    __shared__ float s[NN];
    __shared__ float gate[NN];
    __shared__ int   sel[NN];
    __shared__ float red[NN];
    __shared__ float gm[H2];
    int b = blockIdx.x;
    int t = threadIdx.x;           // 512 threads
    float v = g_score[(size_t)b * NN + t];
    s[t] = v;
    __syncthreads();
    int rank = 0;
    for (int j = 0; j < NN; j++) {
        float u = s[j];
        rank += (u > v) || (u == v && j < t);
    }
    sel[t] = (rank < KSEL);
    gate[t] = tanhf(v);
    __syncthreads();
    int f = t & 127, ch = t >> 7;  // 4 chunks of 128 nodes each
    float m = -INFINITY;
    const float* base = g_out2 + ((size_t)b * NN) * H2;
    for (int i = ch * 128; i < ch * 128 + 128; i++) {
        if (sel[i]) m = fmaxf(m, base[(size_t)i * H2 + f] * gate[i]);
    }
    red[t] = m;
    __syncthreads();
    if (ch == 0) {
        gm[f] = fmaxf(fmaxf(red[f], red[f + 128]), fmaxf(red[f + 256], red[f + 384]));
    }
    __syncthreads();
    // FC + log_softmax (warp 0)
    if (t < 32) {
        float acc = -INFINITY;
        if (t < NC) {
            acc = fcb[t];
            #pragma unroll 8
            for (int k = 0; k < H2; k++) acc += gm[k] * fcW[k * NC + t];
        }
        float mx = acc;
        #pragma unroll
        for (int off = 16; off > 0; off >>= 1) mx = fmaxf(mx, __shfl_xor_sync(0xffffffffu, mx, off));
        float ev = (t < NC) ? expf(acc - mx) : 0.f;
        float sum = ev;
        #pragma unroll
        for (int off = 16; off > 0; off >>= 1) sum += __shfl_xor_sync(0xffffffffu, sum, off);
        if (t < NC) out[(size_t)b * NC + t] = acc - mx - logf(sum);
    }
}

// ---------------- launch ----------------
// hs 32KB + rs (NN+1)*4 + cols 8KB = 43012 B  (< 48KB, no attribute needed)
#define GATHER_SMEM (NN*FQ*4 + (NN+1)*4 + EPG*2)

extern "C" void kernel_launch(void* const* d_in, const int* in_sizes, int n_in,
                              void* d_out, int out_size) {
    const float* x   = (const float*)d_in[0];
    const int*   ei  = (const int*)d_in[1];    // int32 (JAX x64 disabled)
    // d_in[2] = batch (unused; layout is implicit b*512+n)
    const float* W1  = (const float*)d_in[3];
    const float* b1  = (const float*)d_in[4];
    const float* W2  = (const float*)d_in[5];
    const float* b2  = (const float*)d_in[6];
    const float* pw  = (const float*)d_in[7];
    const float* fcW = (const float*)d_in[8];
    const float* fcb = (const float*)d_in[9];
    float*       out = (float*)d_out;

    k_build<<<NB, NN>>>(ei);
    k_gemm1<<<NNODES / 32, dim3(16, 8)>>>(x, W1);
    k_gatherF<<<dim3(NB, 4), NN, GATHER_SMEM>>>(b1);
    k_gemm2<<<NNODES / 64, dim3(32, 8)>>>(W2, b2, pw);
    k_pool<<<NB, NN>>>(fcW, fcb, out);
}